// round 1
// baseline (speedup 1.0000x reference)
#include <cuda_runtime.h>
#include <cuda_bf16.h>

// Direct 3x3 conv, pad=1, fp32. Mathematically identical to the reference's
// FFT path (65x65 grid >= linear size 36, so no circular wrap reaches the crop).
//
// x: [32,128,32,32], w: [128,128,3,3], b: [128] -> out: [32,128,32,32]

#define CBLK 8
#define XS_RSTRIDE 34        // padded row: cols -1..32
#define XS_CSTRIDE 204       // 6 rows * 34
#define WS_STRIDE 129        // 128 filters + 1 pad (kills STS bank conflicts)

__global__ __launch_bounds__(256, 2)
void conv3x3_kernel(const float* __restrict__ x,
                    const float* __restrict__ w,
                    const float* __restrict__ b,
                    float* __restrict__ out) {
    __shared__ float xs[CBLK * 6 * XS_RSTRIDE];   // 1632 floats
    __shared__ float ws[72 * WS_STRIDE];          // 9288 floats

    const int bx   = blockIdx.x;
    const int n    = bx >> 3;       // image
    const int rb   = bx & 7;        // row block (4 rows each)
    const int row0 = rb * 4;

    const int tid    = threadIdx.x;
    const int tf     = tid >> 4;            // 0..15 -> filter group of 8
    const int ts     = tid & 15;            // 0..15 -> spatial group
    const int f_base = tf * 8;
    const int row_l  = ts >> 2;             // 0..3 local row
    const int colb   = (ts & 3) * 8;        // 0,8,16,24

    float acc[8][8];
    #pragma unroll
    for (int j = 0; j < 8; ++j) {
        const float bv = b[f_base + j];
        #pragma unroll
        for (int i = 0; i < 8; ++i) acc[j][i] = bv;
    }

    const float* xn = x + n * (128 * 32 * 32);

    for (int c0 = 0; c0 < 128; c0 += CBLK) {
        __syncthreads();

        // --- load x tile: xs[c][r][colp], colp = global col + 1, zero halo ---
        for (int i = tid; i < CBLK * 6 * XS_RSTRIDE; i += 256) {
            int c   = i / XS_CSTRIDE;
            int rem = i - c * XS_CSTRIDE;
            int r   = rem / XS_RSTRIDE;
            int col = rem - r * XS_RSTRIDE - 1;       // -1..32
            int gr  = row0 - 1 + r;                   // -1..35
            float v = 0.0f;
            if ((unsigned)gr < 32u && (unsigned)col < 32u)
                v = xn[(c0 + c) * 1024 + gr * 32 + col];
            xs[i] = v;
        }

        // --- load w tile transposed: ws[(c'*9+q)*129 + f] = w[f][c0+c'][q] ---
        // global side reads 72 contiguous floats per filter (coalesced-ish),
        // smem side strided by 129 (conflict-free).
        for (int i = tid; i < 128 * 72; i += 256) {
            int f   = i / 72;
            int off = i - f * 72;                     // c'*9 + q, c' in 0..7
            ws[off * WS_STRIDE + f] = w[f * 1152 + c0 * 9 + off];
        }
        __syncthreads();

        #pragma unroll 1
        for (int c = 0; c < CBLK; ++c) {
            const float* xrb = &xs[c * XS_CSTRIDE + row_l * XS_RSTRIDE + colb];
            const float* wcb = &ws[c * 9 * WS_STRIDE + f_base];
            #pragma unroll
            for (int kh = 0; kh < 3; ++kh) {
                float xv[10];
                #pragma unroll
                for (int i = 0; i < 10; ++i)
                    xv[i] = xrb[kh * XS_RSTRIDE + i];   // padded cols colb..colb+9
                #pragma unroll
                for (int kw = 0; kw < 3; ++kw) {
                    const float* wp = wcb + (kh * 3 + kw) * WS_STRIDE;
                    float wv[8];
                    #pragma unroll
                    for (int j = 0; j < 8; ++j) wv[j] = wp[j];
                    #pragma unroll
                    for (int j = 0; j < 8; ++j)
                        #pragma unroll
                        for (int i = 0; i < 8; ++i)
                            acc[j][i] += wv[j] * xv[i + kw];
                }
            }
        }
    }

    // --- store: out[n][f][row0+row_l][colb + 0..7], float4 x2 per filter ---
    float* outp = out + n * (128 * 1024) + (row0 + row_l) * 32 + colb;
    #pragma unroll
    for (int j = 0; j < 8; ++j) {
        float4* o = (float4*)(outp + (f_base + j) * 1024);
        o[0] = make_float4(acc[j][0], acc[j][1], acc[j][2], acc[j][3]);
        o[1] = make_float4(acc[j][4], acc[j][5], acc[j][6], acc[j][7]);
    }
}

extern "C" void kernel_launch(void* const* d_in, const int* in_sizes, int n_in,
                              void* d_out, int out_size) {
    const float* x = (const float*)d_in[0];
    const float* w = (const float*)d_in[1];
    const float* b = (const float*)d_in[2];
    float* out = (float*)d_out;
    conv3x3_kernel<<<256, 256>>>(x, w, b, out);
}

// round 4
// speedup vs baseline: 2.5153x; 2.5153x over previous
#include <cuda_runtime.h>
#include <cuda_bf16.h>
#include <stdint.h>

// ============================================================
// Conv 3x3 pad=1 as bf16-split implicit GEMM on HMMA (mma.sync).
// (tcgen05 unavailable: harness PTX target is compute_103, no 'a' features)
//
// x:[32,128,32,32] w:[128,128,3,3] b:[128] -> out:[32,128,32,32]
// m = h*34 + w (h,w = output coords); input needed: xpad[m + kh*34 + kw][c]
// where xpad is the zero-padded plane in 34x34 row-major (ph = h+1 etc).
// GEMM D[m,f] = A[m,k] B[f,k], k=(q,c), fp32 accum, A/B split bf16 hi+lo,
// 3 products: Ah*Bh + Ah*Bl + Al*Bh.
// ============================================================

#define NPLANE 1156

__device__ __align__(256) __nv_bfloat16 g_xh[32 * NPLANE * 128];
__device__ __align__(256) __nv_bfloat16 g_xl[32 * NPLANE * 128];
__device__ __align__(256) __nv_bfloat16 g_wh[9 * 128 * 128];
__device__ __align__(256) __nv_bfloat16 g_wl[9 * 128 * 128];

__device__ __forceinline__ uint32_t smem_u32(const void* p) {
    uint32_t a;
    asm("{ .reg .u64 t; cvta.to.shared.u64 t, %1; cvt.u32.u64 %0, t; }" : "=r"(a) : "l"(p));
    return a;
}

#define CP_ASYNC16(dst, src, sz) \
    asm volatile("cp.async.cg.shared.global [%0], [%1], 16, %2;" :: "r"(dst), "l"(src), "r"(sz) : "memory")

__device__ __forceinline__ void ldm_x4(uint32_t* r, uint32_t addr) {
    asm volatile("ldmatrix.sync.aligned.m8n8.x4.shared.b16 {%0,%1,%2,%3}, [%4];"
                 : "=r"(r[0]), "=r"(r[1]), "=r"(r[2]), "=r"(r[3]) : "r"(addr));
}

__device__ __forceinline__ void mma_bf16(float* c, const uint32_t* a, const uint32_t* b) {
    asm volatile(
        "mma.sync.aligned.m16n8k16.row.col.f32.bf16.bf16.f32 "
        "{%0,%1,%2,%3}, {%4,%5,%6,%7}, {%8,%9}, {%0,%1,%2,%3};"
        : "+f"(c[0]), "+f"(c[1]), "+f"(c[2]), "+f"(c[3])
        : "r"(a[0]), "r"(a[1]), "r"(a[2]), "r"(a[3]), "r"(b[0]), "r"(b[1]));
}

// ---------------- prep kernels ----------------

__global__ void prep_x(const float* __restrict__ x) {
    __shared__ float s[128][33];
    const int n = blockIdx.y, p0 = blockIdx.x * 32, t = threadIdx.x;
    {
        int c = t >> 1, half = t & 1;
        #pragma unroll
        for (int j = 0; j < 16; ++j) {
            int i = half * 16 + j;
            int p = p0 + i;
            float v = 0.0f;
            if (p < NPLANE) {
                int ph = p / 34, pw = p % 34;
                int h = ph - 1, w = pw - 1;
                if ((unsigned)h < 32u && (unsigned)w < 32u)
                    v = x[((size_t)(n * 128 + c)) * 1024 + h * 32 + w];
            }
            s[c][i] = v;
        }
    }
    __syncthreads();
    {
        int i = t >> 3, cb = (t & 7) * 16;
        int p = p0 + i;
        if (p < NPLANE) {
            __align__(16) __nv_bfloat16 hb[16], lb[16];
            #pragma unroll
            for (int j = 0; j < 16; ++j) {
                float v = s[cb + j][i];
                __nv_bfloat16 h16 = __float2bfloat16(v);
                float r = v - __bfloat162float(h16);
                hb[j] = h16;
                lb[j] = __float2bfloat16(r);
            }
            size_t base = ((size_t)(n * NPLANE + p)) * 128 + cb;
            *(uint4*)(&g_xh[base])     = *(uint4*)(hb);
            *(uint4*)(&g_xh[base + 8]) = *(uint4*)(hb + 8);
            *(uint4*)(&g_xl[base])     = *(uint4*)(lb);
            *(uint4*)(&g_xl[base + 8]) = *(uint4*)(lb + 8);
        }
    }
}

__global__ void prep_w(const float* __restrict__ w) {
    int id = blockIdx.x * 256 + threadIdx.x;
    if (id >= 128 * 128) return;
    int f = id >> 7, c = id & 127;
    const float* wp = w + (size_t)(f * 128 + c) * 9;
    #pragma unroll
    for (int q = 0; q < 9; ++q) {
        float v = wp[q];
        __nv_bfloat16 h16 = __float2bfloat16(v);
        float r = v - __bfloat162float(h16);
        int o = (q * 128 + f) * 128 + c;
        g_wh[o] = h16;
        g_wl[o] = __float2bfloat16(r);
    }
}

// ---------------- main GEMM kernel ----------------
// 288 CTAs: T = blockIdx.x, n = T/9, m0 = (T%9)*128. 256 thr = 8 warps,
// warp grid 2(M)x4(N): warp tile 64x32. K stage = 32 channels; 36 stages.
// Stage layout (halves, row stride 80B = 32 bf16 + 16B pad):
//   Ah[128][80B] @0, Al @10240, Bh @20480, Bl @30720. Stage = 40960B, x2 buf.

#define STAGE_BYTES 40960
#define ROWB 80
#define NUNITS 36

__global__ __launch_bounds__(256)
void conv_hmma(const float* __restrict__ bias, float* __restrict__ out) {
    extern __shared__ char dynsmem[];
    __shared__ float bias_s[128];

    const int tid = threadIdx.x, wid = tid >> 5, lane = tid & 31;
    const int wm = wid >> 2, wn = wid & 3;
    const int T = blockIdx.x;
    const int n = T / 9, m0 = (T % 9) * 128;

    if (tid < 128) bias_s[tid] = bias[tid];

    const uint32_t sd = smem_u32(dynsmem);

    auto load_stage = [&](int u, int s) {
        const int q = u >> 2, c0 = (u & 3) * 32;
        const int shift = (q / 3) * 34 + (q % 3);
        const uint32_t sbase = sd + s * STAGE_BYTES;
        #pragma unroll
        for (int it = 0; it < 8; ++it) {
            int idx = it * 256 + tid;
            int tile = idx >> 9;            // 0..3
            int rem = idx & 511;
            int row = rem >> 2, ch = rem & 3;
            uint32_t dst = sbase + tile * 10240 + row * ROWB + ch * 16;
            const __nv_bfloat16* src;
            int sz = 16;
            if (tile < 2) {
                const __nv_bfloat16* g = tile ? g_xl : g_xh;
                int p = m0 + shift + row;
                if (p >= NPLANE) { p = 0; sz = 0; }
                src = g + ((size_t)(n * NPLANE + p)) * 128 + c0 + ch * 8;
            } else {
                const __nv_bfloat16* g = (tile & 1) ? g_wl : g_wh;
                src = g + (size_t)((q * 128 + row) * 128) + c0 + ch * 8;
            }
            CP_ASYNC16(dst, src, sz);
        }
        asm volatile("cp.async.commit_group;" ::: "memory");
    };

    float acc[4][4][4];
    #pragma unroll
    for (int i = 0; i < 4; ++i)
        #pragma unroll
        for (int j = 0; j < 4; ++j)
            #pragma unroll
            for (int r = 0; r < 4; ++r) acc[i][j][r] = 0.0f;

    // lane-steered ldmatrix offsets
    const uint32_t a_lrow = (uint32_t)(wm * 64 + (lane & 15)) * ROWB + ((lane >> 4) << 4);
    const uint32_t b_lrow = (uint32_t)(wn * 32 + ((lane >> 4) << 3) + (lane & 7)) * ROWB
                            + ((lane & 8) ? 16u : 0u);

    load_stage(0, 0);

    for (int u = 0; u < NUNITS; ++u) {
        if (u + 1 < NUNITS) {
            load_stage(u + 1, (u + 1) & 1);
            asm volatile("cp.async.wait_group 1;" ::: "memory");
        } else {
            asm volatile("cp.async.wait_group 0;" ::: "memory");
        }
        __syncthreads();

        const uint32_t sbase = sd + (u & 1) * STAGE_BYTES;
        #pragma unroll
        for (int ks = 0; ks < 2; ++ks) {
            uint32_t Ah[16], Al[16], Bh[8], Bl[8];
            const uint32_t ao = sbase + a_lrow + ks * 32;
            #pragma unroll
            for (int i = 0; i < 4; ++i) ldm_x4(&Ah[4 * i], ao + i * 16 * ROWB);
            #pragma unroll
            for (int i = 0; i < 4; ++i) ldm_x4(&Al[4 * i], ao + 10240 + i * 16 * ROWB);
            const uint32_t bo = sbase + 20480 + b_lrow + ks * 32;
            ldm_x4(&Bh[0], bo);
            ldm_x4(&Bh[4], bo + 16 * ROWB);
            ldm_x4(&Bl[0], bo + 10240);
            ldm_x4(&Bl[4], bo + 10240 + 16 * ROWB);

            #pragma unroll
            for (int i = 0; i < 4; ++i)
                #pragma unroll
                for (int j = 0; j < 4; ++j) {
                    const uint32_t* bhp = &Bh[(j >> 1) * 4 + (j & 1) * 2];
                    const uint32_t* blp = &Bl[(j >> 1) * 4 + (j & 1) * 2];
                    mma_bf16(acc[i][j], &Ah[4 * i], bhp);
                    mma_bf16(acc[i][j], &Al[4 * i], bhp);
                    mma_bf16(acc[i][j], &Ah[4 * i], blp);
                }
        }
        __syncthreads();   // all warps done reading before buffer reuse
    }

    // ---------------- epilogue via smem (coalesce f-strided stores) ----------
    // per-warp tile [64 m][34 f] floats (8704 B), 8 warps = 69632 <= 81920
    __syncthreads();
    float* eps = (float*)dynsmem + wid * (64 * 34);
    const int g = lane >> 2, tg = lane & 3;
    #pragma unroll
    for (int i = 0; i < 4; ++i)
        #pragma unroll
        for (int j = 0; j < 4; ++j) {
            float* p0 = &eps[(i * 16 + g) * 34 + j * 8 + 2 * tg];
            float* p1 = &eps[(i * 16 + g + 8) * 34 + j * 8 + 2 * tg];
            *(float2*)p0 = make_float2(acc[i][j][0], acc[i][j][1]);
            *(float2*)p1 = make_float2(acc[i][j][2], acc[i][j][3]);
        }
    __syncwarp();

    // m = h*34 + w directly (h,w are OUTPUT coords): valid iff h<32 && w<32
    const int mwbase = m0 + wm * 64;
    float* outn = out + (size_t)n * 128 * 1024;
    #pragma unroll 1
    for (int f = 0; f < 32; ++f) {
        const int fg = wn * 32 + f;
        const float bv = bias_s[fg];
        #pragma unroll
        for (int half = 0; half < 2; ++half) {
            int ml = half * 32 + lane;
            int m = mwbase + ml;
            int hh = m / 34, ww = m % 34;
            if (hh < 32 && ww < 32)
                outn[(size_t)fg * 1024 + hh * 32 + ww] = eps[ml * 34 + f] + bv;
        }
    }
}

// ---------------- launch ----------------

extern "C" void kernel_launch(void* const* d_in, const int* in_sizes, int n_in,
                              void* d_out, int out_size) {
    const float* x = (const float*)d_in[0];
    const float* w = (const float*)d_in[1];
    const float* b = (const float*)d_in[2];
    float* out = (float*)d_out;

    cudaFuncSetAttribute(conv_hmma, cudaFuncAttributeMaxDynamicSharedMemorySize, 2 * STAGE_BYTES);

    dim3 gx(37, 32);
    prep_x<<<gx, 256>>>(x);
    prep_w<<<64, 256>>>(w);
    conv_hmma<<<288, 256, 2 * STAGE_BYTES>>>(b, out);
}

// round 6
// speedup vs baseline: 5.7809x; 2.2983x over previous
#include <cuda_runtime.h>
#include <cuda_fp16.h>
#include <stdint.h>

// ============================================================
// Conv 3x3 pad=1 as fp16 single-product implicit GEMM on HMMA.
// x:[32,128,32,32] w:[128,128,3,3] b:[128] -> out:[32,128,32,32]
// m = h*34 + w (output coords); A[m,k] = xpad[m + kh*34 + kw][c] (fp16)
// B[f,k] = w[f][c][kh,kw] (fp16), fp32 accumulate.
// Error model (calibrated R4): rel_err ~ sqrt(2)*2^-11/sqrt(3) ~ 4e-4 < 1e-3.
// ============================================================

#define NPLANE 1156

__device__ __align__(256) __half g_xh[32 * NPLANE * 128];
__device__ __align__(256) __half g_wh[9 * 128 * 128];

__device__ __forceinline__ uint32_t smem_u32(const void* p) {
    uint32_t a;
    asm("{ .reg .u64 t; cvta.to.shared.u64 t, %1; cvt.u32.u64 %0, t; }" : "=r"(a) : "l"(p));
    return a;
}

#define CP_ASYNC16(dst, src, sz) \
    asm volatile("cp.async.cg.shared.global [%0], [%1], 16, %2;" :: "r"(dst), "l"(src), "r"(sz) : "memory")

__device__ __forceinline__ void ldm_x4(uint32_t* r, uint32_t addr) {
    asm volatile("ldmatrix.sync.aligned.m8n8.x4.shared.b16 {%0,%1,%2,%3}, [%4];"
                 : "=r"(r[0]), "=r"(r[1]), "=r"(r[2]), "=r"(r[3]) : "r"(addr));
}

__device__ __forceinline__ void mma_f16(float* c, const uint32_t* a, const uint32_t* b) {
    asm volatile(
        "mma.sync.aligned.m16n8k16.row.col.f32.f16.f16.f32 "
        "{%0,%1,%2,%3}, {%4,%5,%6,%7}, {%8,%9}, {%0,%1,%2,%3};"
        : "+f"(c[0]), "+f"(c[1]), "+f"(c[2]), "+f"(c[3])
        : "r"(a[0]), "r"(a[1]), "r"(a[2]), "r"(a[3]), "r"(b[0]), "r"(b[1]));
}

// ---------------- prep kernels ----------------

__global__ void prep_x(const float* __restrict__ x) {
    __shared__ float s[128][33];
    const int n = blockIdx.y, p0 = blockIdx.x * 32, t = threadIdx.x;
    const int lane = t & 31, wrp = t >> 5;

    {   // phase 1: warp loads 32 consecutive p per c (fully coalesced)
        int p = p0 + lane;
        int ph = p / 34, pw = p - ph * 34;
        int h = ph - 1, w = pw - 1;
        bool ok = (p < NPLANE) && ((unsigned)h < 32u) && ((unsigned)w < 32u);
        const float* xb = x + ((size_t)n * 128) * 1024 + h * 32 + w;
        #pragma unroll
        for (int k = 0; k < 16; ++k) {
            int c = wrp * 16 + k;
            s[c][lane] = ok ? xb[(size_t)c * 1024] : 0.0f;
        }
    }
    __syncthreads();
    {   // phase 2: lane indexes p (conflict-free smem reads), 32B stores
        int i = lane, cb = wrp * 16;
        int p = p0 + i;
        if (p < NPLANE) {
            __align__(16) __half hb[16];
            #pragma unroll
            for (int j = 0; j < 16; ++j) hb[j] = __float2half(s[cb + j][i]);
            size_t base = ((size_t)(n * NPLANE + p)) * 128 + cb;
            *(uint4*)(&g_xh[base])     = *(uint4*)(hb);
            *(uint4*)(&g_xh[base + 8]) = *(uint4*)(hb + 8);
        }
    }
}

__global__ void prep_w(const float* __restrict__ w) {
    int id = blockIdx.x * 256 + threadIdx.x;
    if (id >= 128 * 128) return;
    int f = id >> 7, c = id & 127;
    const float* wp = w + (size_t)(f * 128 + c) * 9;
    #pragma unroll
    for (int q = 0; q < 9; ++q)
        g_wh[(q * 128 + f) * 128 + c] = __float2half(wp[q]);
}

// ---------------- main GEMM kernel ----------------
// 288 CTAs: T = blockIdx.x, n = T/9, m0 = (T%9)*128. 8 warps, warp grid
// 2(M)x4(N), warp tile 64x32. K stage = 32 channels (tap q, chunk); 36 stages.
// Stage: A[128][80B] @0, B[128][80B] @10240. STAGE=20480B, double buffered.
// Epilogue reuses dynsmem: per-warp [64 m][18] floats (even stride -> float2
// stays 8B-aligned; stride-17 in R5 caused the misaligned-address fault).

#define STAGE_BYTES 20480
#define ROWB 80
#define NUNITS 36
#define EPSTRIDE 18

__global__ __launch_bounds__(256, 2)
void conv_hmma(const float* __restrict__ bias, float* __restrict__ out) {
    extern __shared__ char dynsmem[];
    __shared__ float bias_s[128];

    const int tid = threadIdx.x, wid = tid >> 5, lane = tid & 31;
    const int wm = wid >> 2, wn = wid & 3;
    const int T = blockIdx.x;
    const int n = T / 9, m0 = (T % 9) * 128;

    if (tid < 128) bias_s[tid] = bias[tid];

    const uint32_t sd = smem_u32(dynsmem);

    auto load_stage = [&](int u, int s) {
        const int q = u >> 2, c0 = (u & 3) * 32;
        const int shift = (q / 3) * 34 + (q % 3);
        const uint32_t sbase = sd + s * STAGE_BYTES;
        #pragma unroll
        for (int it = 0; it < 4; ++it) {
            int idx = it * 256 + tid;
            int tile = idx >> 9;            // 0..1
            int rem = idx & 511;
            int row = rem >> 2, ch = rem & 3;
            uint32_t dst = sbase + tile * 10240 + row * ROWB + ch * 16;
            const __half* src;
            int sz = 16;
            if (tile == 0) {
                int p = m0 + shift + row;
                if (p >= NPLANE) { p = 0; sz = 0; }
                src = g_xh + ((size_t)(n * NPLANE + p)) * 128 + c0 + ch * 8;
            } else {
                src = g_wh + (size_t)((q * 128 + row) * 128) + c0 + ch * 8;
            }
            CP_ASYNC16(dst, src, sz);
        }
        asm volatile("cp.async.commit_group;" ::: "memory");
    };

    float acc[4][4][4];
    #pragma unroll
    for (int i = 0; i < 4; ++i)
        #pragma unroll
        for (int j = 0; j < 4; ++j)
            #pragma unroll
            for (int r = 0; r < 4; ++r) acc[i][j][r] = 0.0f;

    const uint32_t a_lrow = (uint32_t)(wm * 64 + (lane & 15)) * ROWB + ((lane >> 4) << 4);
    const uint32_t b_lrow = (uint32_t)(wn * 32 + ((lane >> 4) << 3) + (lane & 7)) * ROWB
                            + ((lane & 8) ? 16u : 0u);

    load_stage(0, 0);

    for (int u = 0; u < NUNITS; ++u) {
        if (u + 1 < NUNITS) {
            load_stage(u + 1, (u + 1) & 1);
            asm volatile("cp.async.wait_group 1;" ::: "memory");
        } else {
            asm volatile("cp.async.wait_group 0;" ::: "memory");
        }
        __syncthreads();

        const uint32_t sbase = sd + (u & 1) * STAGE_BYTES;
        #pragma unroll
        for (int ks = 0; ks < 2; ++ks) {
            uint32_t Ah[16], Bh[8];
            const uint32_t ao = sbase + a_lrow + ks * 32;
            #pragma unroll
            for (int i = 0; i < 4; ++i) ldm_x4(&Ah[4 * i], ao + i * 16 * ROWB);
            const uint32_t bo = sbase + 10240 + b_lrow + ks * 32;
            ldm_x4(&Bh[0], bo);
            ldm_x4(&Bh[4], bo + 16 * ROWB);

            #pragma unroll
            for (int i = 0; i < 4; ++i)
                #pragma unroll
                for (int j = 0; j < 4; ++j)
                    mma_f16(acc[i][j], &Ah[4 * i], &Bh[(j >> 1) * 4 + (j & 1) * 2]);
        }
        __syncthreads();   // all warps done reading before buffer reuse
    }

    // ---------------- epilogue: 2 f-chunks of 16 via smem ----------------
    float* eps = (float*)dynsmem + wid * (64 * EPSTRIDE);   // 4608B/warp, 36864 total
    const int g = lane >> 2, tg = lane & 3;
    const int mwbase = m0 + wm * 64;
    float* outn = out + (size_t)n * 128 * 1024;

    #pragma unroll
    for (int cj = 0; cj < 2; ++cj) {
        __syncwarp();
        #pragma unroll
        for (int i = 0; i < 4; ++i)
            #pragma unroll
            for (int jj = 0; jj < 2; ++jj) {
                int j = cj * 2 + jj;
                float* p0 = &eps[(i * 16 + g) * EPSTRIDE + jj * 8 + 2 * tg];
                float* p1 = &eps[(i * 16 + g + 8) * EPSTRIDE + jj * 8 + 2 * tg];
                *(float2*)p0 = make_float2(acc[i][j][0], acc[i][j][1]);
                *(float2*)p1 = make_float2(acc[i][j][2], acc[i][j][3]);
            }
        __syncwarp();

        #pragma unroll 1
        for (int f = 0; f < 16; ++f) {
            const int fg = wn * 32 + cj * 16 + f;
            const float bv = bias_s[fg];
            #pragma unroll
            for (int half = 0; half < 2; ++half) {
                int ml = half * 32 + lane;
                int m = mwbase + ml;
                int hh = m / 34, ww = m % 34;
                if (hh < 32 && ww < 32)
                    outn[(size_t)fg * 1024 + hh * 32 + ww] = eps[ml * EPSTRIDE + f] + bv;
            }
        }
    }
}

// ---------------- launch ----------------

extern "C" void kernel_launch(void* const* d_in, const int* in_sizes, int n_in,
                              void* d_out, int out_size) {
    const float* x = (const float*)d_in[0];
    const float* w = (const float*)d_in[1];
    const float* b = (const float*)d_in[2];
    float* out = (float*)d_out;

    cudaFuncSetAttribute(conv_hmma, cudaFuncAttributeMaxDynamicSharedMemorySize, 2 * STAGE_BYTES);

    dim3 gx(37, 32);
    prep_x<<<gx, 256>>>(x);
    prep_w<<<64, 256>>>(w);
    conv_hmma<<<288, 256, 2 * STAGE_BYTES>>>(b, out);
}

// round 7
// speedup vs baseline: 7.2083x; 1.2469x over previous
#include <cuda_runtime.h>
#include <cuda_fp16.h>
#include <stdint.h>

// ============================================================
// Conv 3x3 pad=1 as fp16 implicit GEMM on HMMA, A-union tiling.
// x:[32,128,32,32] w:[128,128,3,3] b:[128] -> out:[32,128,32,32]
// m = h*34 + w (output coords); A[m,k] = xpad[m + kh*34 + kw][c]
// A-union: rows [m0, m0+203] cover all 9 tap shifts (max shift 70 + 127).
// 18 units = 9 taps x 2 chunks of 64 channels; per-tap A = smem offset only.
// ============================================================

#define NPLANE 1156

__device__ __align__(256) __half g_xh[32 * NPLANE * 128];
__device__ __align__(256) __half g_wh[9 * 128 * 128];

__device__ __forceinline__ uint32_t smem_u32(const void* p) {
    uint32_t a;
    asm("{ .reg .u64 t; cvta.to.shared.u64 t, %1; cvt.u32.u64 %0, t; }" : "=r"(a) : "l"(p));
    return a;
}

#define CP_ASYNC16(dst, src, sz) \
    asm volatile("cp.async.cg.shared.global [%0], [%1], 16, %2;" :: "r"(dst), "l"(src), "r"(sz) : "memory")

__device__ __forceinline__ void ldm_x4(uint32_t* r, uint32_t addr) {
    asm volatile("ldmatrix.sync.aligned.m8n8.x4.shared.b16 {%0,%1,%2,%3}, [%4];"
                 : "=r"(r[0]), "=r"(r[1]), "=r"(r[2]), "=r"(r[3]) : "r"(addr));
}

__device__ __forceinline__ void mma_f16(float* c, const uint32_t* a, const uint32_t* b) {
    asm volatile(
        "mma.sync.aligned.m16n8k16.row.col.f32.f16.f16.f32 "
        "{%0,%1,%2,%3}, {%4,%5,%6,%7}, {%8,%9}, {%0,%1,%2,%3};"
        : "+f"(c[0]), "+f"(c[1]), "+f"(c[2]), "+f"(c[3])
        : "r"(a[0]), "r"(a[1]), "r"(a[2]), "r"(a[3]), "r"(b[0]), "r"(b[1]));
}

// ---------------- merged prep kernel ----------------
// grid (38, 32): bx<37 -> x transpose/convert; bx==37 -> weight transpose.

__global__ void prep_all(const float* __restrict__ x, const float* __restrict__ w) {
    const int bx = blockIdx.x, n = blockIdx.y, t = threadIdx.x;

    if (bx == 37) {   // weights: 32 blocks x 256 threads, 2 (f,c) pairs each
        #pragma unroll
        for (int r = 0; r < 2; ++r) {
            int id = n * 256 + t + r * 8192;
            int f = id >> 7, c = id & 127;
            const float* wp = w + (size_t)(f * 128 + c) * 9;
            #pragma unroll
            for (int q = 0; q < 9; ++q)
                g_wh[(q * 128 + f) * 128 + c] = __float2half(wp[q]);
        }
        return;
    }

    __shared__ float s[128][33];
    const int p0 = bx * 32;
    const int lane = t & 31, wrp = t >> 5;

    {   // phase 1: warp loads 32 consecutive p per c (fully coalesced)
        int p = p0 + lane;
        int ph = p / 34, pw = p - ph * 34;
        int h = ph - 1, ww = pw - 1;
        bool ok = (p < NPLANE) && ((unsigned)h < 32u) && ((unsigned)ww < 32u);
        const float* xb = x + ((size_t)n * 128) * 1024 + h * 32 + ww;
        #pragma unroll
        for (int k = 0; k < 16; ++k) {
            int c = wrp * 16 + k;
            s[c][lane] = ok ? xb[(size_t)c * 1024] : 0.0f;
        }
    }
    __syncthreads();
    {   // phase 2: conflict-free smem reads, 32B contiguous stores
        int i = lane, cb = wrp * 16;
        int p = p0 + i;
        if (p < NPLANE) {
            __align__(16) __half hb[16];
            #pragma unroll
            for (int j = 0; j < 16; ++j) hb[j] = __float2half(s[cb + j][i]);
            size_t base = ((size_t)(n * NPLANE + p)) * 128 + cb;
            *(uint4*)(&g_xh[base])     = *(uint4*)(hb);
            *(uint4*)(&g_xh[base + 8]) = *(uint4*)(hb + 8);
        }
    }
}

// ---------------- main GEMM kernel ----------------
// 288 CTAs: T = blockIdx.x, n = T/9, m0 = (T%9)*128. 8 warps, 2(M)x4(N),
// warp tile 64x32.
// SMEM (rows 144B = 128B data + 16B pad; conflict-free for ldmatrix):
//   A-union chunk buffers: 2 x [204 rows][144B] = 2 x 29376 @0
//   B ring:                2 x [128 rows][144B] = 2 x 18432 @58752
// Unit u (0..17): chunk = u/9 (c0 = chunk*64), q = u%9.
// Loop: wait_group 0 -> syncthreads -> issue B(u+1) -> compute(u).

#define ROWB 144
#define A_STAGE 29376
#define B_BASE 58752
#define B_STAGE 18432
#define SMEM_DYN 95616
#define NUNITS 18
#define EPSTRIDE 18

__global__ __launch_bounds__(256, 2)
void conv_hmma(const float* __restrict__ bias, float* __restrict__ out) {
    extern __shared__ char dynsmem[];
    __shared__ float bias_s[128];

    const int tid = threadIdx.x, wid = tid >> 5, lane = tid & 31;
    const int wm = wid >> 2, wn = wid & 3;
    const int T = blockIdx.x;
    const int n = T / 9, m0 = (T % 9) * 128;

    if (tid < 128) bias_s[tid] = bias[tid];

    const uint32_t sd = smem_u32(dynsmem);

    // A-union load: 204 rows x 8 x 16B = 1632 chunks, 7 iters x 256 thr
    auto load_A = [&](int chunk) {
        const uint32_t abase = sd + chunk * A_STAGE;
        const int c0 = chunk * 64;
        #pragma unroll
        for (int it = 0; it < 7; ++it) {
            int idx = it * 256 + tid;
            if (idx < 1632) {
                int row = idx >> 3, ch = idx & 7;
                int p = m0 + row;
                int sz = 16;
                if (p >= NPLANE) { p = 0; sz = 0; }
                CP_ASYNC16(abase + row * ROWB + ch * 16,
                           g_xh + ((size_t)(n * NPLANE + p)) * 128 + c0 + ch * 8, sz);
            }
        }
        asm volatile("cp.async.commit_group;" ::: "memory");
    };

    // B stage load: q, chunk -> slot u&1; 128 rows x 8 x 16B = 1024 chunks
    auto load_B = [&](int u) {
        const int q = u % 9, chunk = u / 9, c0 = chunk * 64;
        const uint32_t bbase = sd + B_BASE + (u & 1) * B_STAGE;
        #pragma unroll
        for (int it = 0; it < 4; ++it) {
            int idx = it * 256 + tid;
            int row = idx >> 3, ch = idx & 7;
            CP_ASYNC16(bbase + row * ROWB + ch * 16,
                       g_wh + (size_t)((q * 128 + row) * 128) + c0 + ch * 8, 16);
        }
        asm volatile("cp.async.commit_group;" ::: "memory");
    };

    float acc[4][4][4];
    #pragma unroll
    for (int i = 0; i < 4; ++i)
        #pragma unroll
        for (int j = 0; j < 4; ++j)
            #pragma unroll
            for (int r = 0; r < 4; ++r) acc[i][j][r] = 0.0f;

    const uint32_t a_lrow = (uint32_t)(wm * 64 + (lane & 15)) * ROWB + ((lane >> 4) << 4);
    const uint32_t b_lrow = (uint32_t)(wn * 32 + ((lane >> 4) << 3) + (lane & 7)) * ROWB
                            + ((lane & 8) ? 16u : 0u);

    // prologue: both A chunks + first two B stages
    load_A(0);
    load_A(1);
    load_B(0);
    load_B(1);

    for (int u = 0; u < NUNITS; ++u) {
        asm volatile("cp.async.wait_group 0;" ::: "memory");
        __syncthreads();                    // data visible + all warps past compute(u-1)
        if (u + 1 < NUNITS) load_B(u + 1);  // overwrites slot read at compute(u-1): safe

        const int q = u % 9, chunk = u / 9;
        const int shift = (q / 3) * 34 + (q % 3);
        const uint32_t abase = sd + chunk * A_STAGE + (uint32_t)shift * ROWB + a_lrow;
        const uint32_t bbase = sd + B_BASE + (u & 1) * B_STAGE + b_lrow;

        #pragma unroll
        for (int ks = 0; ks < 4; ++ks) {
            uint32_t Ah[16], Bh[8];
            const uint32_t ao = abase + ks * 32;
            #pragma unroll
            for (int i = 0; i < 4; ++i) ldm_x4(&Ah[4 * i], ao + i * 16 * ROWB);
            const uint32_t bo = bbase + ks * 32;
            ldm_x4(&Bh[0], bo);
            ldm_x4(&Bh[4], bo + 16 * ROWB);

            #pragma unroll
            for (int i = 0; i < 4; ++i)
                #pragma unroll
                for (int j = 0; j < 4; ++j)
                    mma_f16(acc[i][j], &Ah[4 * i], &Bh[(j >> 1) * 4 + (j & 1) * 2]);
        }
    }

    __syncthreads();   // all warps done with smem before epilogue reuse

    // ---------------- epilogue: 2 f-chunks of 16 via smem ----------------
    float* eps = (float*)dynsmem + wid * (64 * EPSTRIDE);
    const int g = lane >> 2, tg = lane & 3;
    const int mwbase = m0 + wm * 64;
    float* outn = out + (size_t)n * 128 * 1024;

    #pragma unroll
    for (int cj = 0; cj < 2; ++cj) {
        __syncwarp();
        #pragma unroll
        for (int i = 0; i < 4; ++i)
            #pragma unroll
            for (int jj = 0; jj < 2; ++jj) {
                int j = cj * 2 + jj;
                float* p0 = &eps[(i * 16 + g) * EPSTRIDE + jj * 8 + 2 * tg];
                float* p1 = &eps[(i * 16 + g + 8) * EPSTRIDE + jj * 8 + 2 * tg];
                *(float2*)p0 = make_float2(acc[i][j][0], acc[i][j][1]);
                *(float2*)p1 = make_float2(acc[i][j][2], acc[i][j][3]);
            }
        __syncwarp();

        #pragma unroll 1
        for (int f = 0; f < 16; ++f) {
            const int fg = wn * 32 + cj * 16 + f;
            const float bv = bias_s[fg];
            #pragma unroll
            for (int half = 0; half < 2; ++half) {
                int ml = half * 32 + lane;
                int m = mwbase + ml;
                int hh = m / 34, ww = m % 34;
                if (hh < 32 && ww < 32)
                    outn[(size_t)fg * 1024 + hh * 32 + ww] = eps[ml * EPSTRIDE + f] + bv;
            }
        }
    }
}

// ---------------- launch ----------------

extern "C" void kernel_launch(void* const* d_in, const int* in_sizes, int n_in,
                              void* d_out, int out_size) {
    const float* x = (const float*)d_in[0];
    const float* w = (const float*)d_in[1];
    const float* b = (const float*)d_in[2];
    float* out = (float*)d_out;

    cudaFuncSetAttribute(conv_hmma, cudaFuncAttributeMaxDynamicSharedMemorySize, SMEM_DYN);

    dim3 gp(38, 32);
    prep_all<<<gp, 256>>>(x, w);
    conv_hmma<<<288, 256, SMEM_DYN>>>(b, out);
}